// round 7
// baseline (speedup 1.0000x reference)
#include <cuda_runtime.h>
#include <cstdint>

// MaskLayer: per-(batch,channel) spatial argmax -> L1-distance mask -> scale.
// x, out: [B, 14, 14, 512] float32, channel-innermost.
//
// R6: keep R5's winning structure (one-shot CTAs, DTILE=64, 4 CTAs/SM) but
// cut warp-instruction count: phase B runs on tid<64 only (1 thread/channel),
// phase C hoists the per-thread sidx vector out of the loop and computes the
// mask entirely on the fma pipe (free |.| source modifiers, no I2F/int-div),
// with incremental (i,j) tracking.

static constexpr int IMGS     = 14;
static constexpr int SPATIAL  = IMGS * IMGS;              // 196
static constexpr int DEPTH    = 512;
static constexpr int DTILE    = 64;                       // channels per CTA
static constexpr int BLOCK    = 128;
static constexpr int TILE_FLOATS = SPATIAL * DTILE;       // 12544
static constexpr int TILE_VEC4   = TILE_FLOATS / 4;       // 3136
static constexpr int ITERS    = (TILE_VEC4 + BLOCK - 1) / BLOCK;  // 25 (last: warps 0-1)
static constexpr int SMEM_BYTES = TILE_FLOATS * (int)sizeof(float);  // 50176

static constexpr float NEG_BIG = -3.402823466e38f;

__device__ __forceinline__ uint32_t smem_u32(const void* p) {
    return (uint32_t)__cvta_generic_to_shared(p);
}

__global__ void __launch_bounds__(BLOCK, 4)
mask_layer_kernel(const float* __restrict__ x, float* __restrict__ out) {
    extern __shared__ float tile[];        // [SPATIAL][DTILE]
    __shared__ int sidx[DTILE];            // packed (row | col<<16) per channel

    const int tid = threadIdx.x;
    const int dt  = blockIdx.x & 7;        // DEPTH / DTILE = 8 tiles per batch
    const int b   = blockIdx.x >> 3;
    const size_t base = (size_t)b * (SPATIAL * DEPTH) + (size_t)dt * DTILE;
    const float* __restrict__ src = x + base;

    // ---- Phase A: stage tile via cp.async.cg (16B, L1-bypass) ----
    // idx -> (s = idx>>4, c4 = (idx&15)*4). Each spatial position is 256B
    // contiguous in gmem; a warp covers 2 positions (512B). Smem conflict-free.
#pragma unroll
    for (int k = 0; k < ITERS; k++) {
        int idx = tid + k * BLOCK;
        if (idx < TILE_VEC4) {             // warp-uniform (k=24: warps 0-1 only)
            int s  = idx >> 4;
            int c4 = (idx & 15) << 2;
            uint32_t d = smem_u32(tile + s * DTILE + c4);
            const float* g = src + (size_t)s * DEPTH + c4;
            asm volatile("cp.async.cg.shared.global [%0], [%1], 16;\n"
                         :: "r"(d), "l"(g));
        }
    }
    asm volatile("cp.async.commit_group;\ncp.async.wait_group 0;\n" ::: "memory");
    __syncthreads();

    // ---- Phase B: per-channel argmax(rowmax) / argmax(colmax) ----
    // One thread per channel (tid<64); warps 2-3 idle at the barrier, halving
    // phase-B warp-instructions. Conflict-free LDS (bank = tid%32).
    // Strict '>' with ascending index == jnp.argmax first-occurrence.
    if (tid < DTILE) {
        float colmax[IMGS];
#pragma unroll
        for (int j = 0; j < IMGS; j++) colmax[j] = NEG_BIG;

        float bestRow = NEG_BIG;
        int rowIdx = 0;
#pragma unroll 2
        for (int i = 0; i < IMGS; i++) {
            float rmax = NEG_BIG;
#pragma unroll
            for (int j = 0; j < IMGS; j++) {
                float v = tile[(i * IMGS + j) * DTILE + tid];
                rmax = fmaxf(rmax, v);
                colmax[j] = fmaxf(colmax[j], v);
            }
            if (rmax > bestRow) { bestRow = rmax; rowIdx = i; }
        }
        int colIdx = 0;
        float bestCol = colmax[0];
#pragma unroll
        for (int j = 1; j < IMGS; j++)
            if (colmax[j] > bestCol) { bestCol = colmax[j]; colIdx = j; }

        sidx[tid] = rowIdx | (colIdx << 16);
    }
    __syncthreads();

    // ---- Phase C: apply mask, vectorized 16B stores ----
    // Per-thread channel quad c4 = (tid&15)*4 is loop-invariant: load the
    // packed argmax vector ONCE and unpack to floats. (i,j) tracked
    // incrementally (s advances by 8 each iter; 8 < 14 so one carry test).
    // mask = TAU*max(1 - COEF*l1, -1) = max(TAU - (TAU*COEF)*l1, -TAU),
    // l1 = |fi-fr| + |fj-fc| -> FADD/FFMA/FMNMX only (abs mods are free).
    {
        const float TAUF = 0.5f / 196.0f;               // TAU
        const float TC   = TAUF * (4.0f / 14.0f);       // TAU * BETA / IMG_SIZE

        const int c4 = (tid & 15) << 2;
        const int s0 = tid >> 4;                        // 0..7

        int4 p = *(const int4*)(sidx + c4);
        const float fr0 = (float)(p.x & 0xFFFF), fc0 = (float)(p.x >> 16);
        const float fr1 = (float)(p.y & 0xFFFF), fc1 = (float)(p.y >> 16);
        const float fr2 = (float)(p.z & 0xFFFF), fc2 = (float)(p.z >> 16);
        const float fr3 = (float)(p.w & 0xFFFF), fc3 = (float)(p.w >> 16);

        float* __restrict__ dstg = out + base;

        int   s  = s0;
        float fi = 0.0f;
        float fj = (float)s0;                           // s0 < 14 -> i=0, j=s0

#pragma unroll
        for (int k = 0; k < ITERS; k++) {
            if (s < SPATIAL) {                          // k=24: warps 0-1 only
                float4 v = *(const float4*)(tile + s * DTILE + c4);

                auto msk = [&](float fr, float fc) -> float {
                    float di = fi - fr;
                    float dj = fj - fc;
                    float l1 = fabsf(di) + fabsf(dj);   // free src-abs mods
                    return fmaxf(fmaf(l1, -TC, TAUF), -TAUF);
                };

                float4 o;
                o.x = msk(fr0, fc0) * v.x;
                o.y = msk(fr1, fc1) * v.y;
                o.z = msk(fr2, fc2) * v.z;
                o.w = msk(fr3, fc3) * v.w;
                *(float4*)(dstg + (size_t)s * DEPTH + c4) = o;
            }
            s += 8;
            fj += 8.0f;
            if (fj >= (float)IMGS) { fj -= (float)IMGS; fi += 1.0f; }
        }
    }
}

extern "C" void kernel_launch(void* const* d_in, const int* in_sizes, int n_in,
                              void* d_out, int out_size) {
    (void)n_in; (void)out_size;
    const float* x = (const float*)d_in[0];
    float* out = (float*)d_out;

    int n = in_sizes[0];                                  // B * 196 * 512
    int batches = n / (SPATIAL * DEPTH);                  // 1024
    int grid = batches * (DEPTH / DTILE);                 // 8192

    // Host-side attribute call: immediate, deterministic, capture-safe.
    cudaFuncSetAttribute(mask_layer_kernel,
                         cudaFuncAttributeMaxDynamicSharedMemorySize, SMEM_BYTES);

    mask_layer_kernel<<<grid, BLOCK, SMEM_BYTES>>>(x, out);
}

// round 8
// speedup vs baseline: 1.0026x; 1.0026x over previous
#include <cuda_runtime.h>
#include <cstdint>

// MaskLayer: per-(batch,channel) spatial argmax -> L1-distance mask -> scale.
// x, out: [B, 14, 14, 512] float32, channel-innermost.
//
// R7: DTILE=32 -> 25KB smem/CTA -> 8 CTAs/SM (launch_bounds(128,8)).
// Eight independent CTAs per SM in uncorrelated load/reduce/store phases keep
// the HBM read and write streams continuously fed (R6 evidence: issue slack
// is ample; the ~16% DRAM idle must come from per-CTA phase gaps).

static constexpr int IMGS     = 14;
static constexpr int SPATIAL  = IMGS * IMGS;              // 196
static constexpr int DEPTH    = 512;
static constexpr int DTILE    = 32;                       // channels per CTA
static constexpr int BLOCK    = 128;
static constexpr int TILE_FLOATS = SPATIAL * DTILE;       // 6272
static constexpr int TILE_VEC4   = TILE_FLOATS / 4;       // 1568
static constexpr int ITERS    = (TILE_VEC4 + BLOCK - 1) / BLOCK;  // 13 (last: warp 0)
static constexpr int SMEM_BYTES = TILE_FLOATS * (int)sizeof(float);  // 25088

static constexpr float NEG_BIG = -3.402823466e38f;

__device__ __forceinline__ uint32_t smem_u32(const void* p) {
    return (uint32_t)__cvta_generic_to_shared(p);
}

__global__ void __launch_bounds__(BLOCK, 8)
mask_layer_kernel(const float* __restrict__ x, float* __restrict__ out) {
    extern __shared__ float tile[];        // [SPATIAL][DTILE]
    __shared__ int sidx[DTILE];            // packed (row | col<<16) per channel

    const int tid = threadIdx.x;
    const int dt  = blockIdx.x & 15;       // DEPTH / DTILE = 16 tiles per batch
    const int b   = blockIdx.x >> 4;
    const size_t base = (size_t)b * (SPATIAL * DEPTH) + (size_t)dt * DTILE;
    const float* __restrict__ src = x + base;

    // ---- Phase A: stage tile via cp.async.cg (16B, L1-bypass) ----
    // idx -> (s = idx>>3, c4 = (idx&7)*4). Each spatial position is 128B
    // contiguous in gmem; a warp covers 4 full 128B lines. Smem conflict-free.
#pragma unroll
    for (int k = 0; k < ITERS; k++) {
        int idx = tid + k * BLOCK;
        if (idx < TILE_VEC4) {             // warp-uniform (k=12: warp 0 only)
            int s  = idx >> 3;
            int c4 = (idx & 7) << 2;
            uint32_t d = smem_u32(tile + s * DTILE + c4);
            const float* g = src + (size_t)s * DEPTH + c4;
            asm volatile("cp.async.cg.shared.global [%0], [%1], 16;\n"
                         :: "r"(d), "l"(g));
        }
    }
    asm volatile("cp.async.commit_group;\ncp.async.wait_group 0;\n" ::: "memory");
    __syncthreads();

    // ---- Phase B: per-channel argmax(rowmax) / argmax(colmax) ----
    // One warp (tid<32), one thread per channel; conflict-free LDS.
    // Strict '>' with ascending index == jnp.argmax first-occurrence.
    if (tid < DTILE) {
        float colmax[IMGS];
#pragma unroll
        for (int j = 0; j < IMGS; j++) colmax[j] = NEG_BIG;

        float bestRow = NEG_BIG;
        int rowIdx = 0;
#pragma unroll 2
        for (int i = 0; i < IMGS; i++) {
            float rmax = NEG_BIG;
#pragma unroll
            for (int j = 0; j < IMGS; j++) {
                float v = tile[(i * IMGS + j) * DTILE + tid];
                rmax = fmaxf(rmax, v);
                colmax[j] = fmaxf(colmax[j], v);
            }
            if (rmax > bestRow) { bestRow = rmax; rowIdx = i; }
        }
        int colIdx = 0;
        float bestCol = colmax[0];
#pragma unroll
        for (int j = 1; j < IMGS; j++)
            if (colmax[j] > bestCol) { bestCol = colmax[j]; colIdx = j; }

        sidx[tid] = rowIdx | (colIdx << 16);
    }
    __syncthreads();

    // ---- Phase C: apply mask, vectorized 16B stores ----
    // Per-thread channel quad c4 = (tid&7)*4 is loop-invariant: load the
    // packed argmax vector ONCE, unpack to floats. (i,j) tracked
    // incrementally in float (s += 16 per iter: one unconditional wrap of 14
    // plus one conditional). mask = max(TAU - (TAU*COEF)*l1, -TAU),
    // l1 = |fi-fr| + |fj-fc| -> FADD/FFMA/FMNMX only (src-abs mods free).
    {
        const float TAUF = 0.5f / 196.0f;               // TAU
        const float TC   = TAUF * (4.0f / 14.0f);       // TAU * BETA / IMG_SIZE

        const int c4 = (tid & 7) << 2;
        const int s0 = tid >> 3;                        // 0..15

        int4 p = *(const int4*)(sidx + c4);
        const float fr0 = (float)(p.x & 0xFFFF), fc0 = (float)(p.x >> 16);
        const float fr1 = (float)(p.y & 0xFFFF), fc1 = (float)(p.y >> 16);
        const float fr2 = (float)(p.z & 0xFFFF), fc2 = (float)(p.z >> 16);
        const float fr3 = (float)(p.w & 0xFFFF), fc3 = (float)(p.w >> 16);

        float* __restrict__ dstg = out + base;

        int   s  = s0;
        float fi = (s0 >= IMGS) ? 1.0f : 0.0f;
        float fj = (float)s0 - fi * (float)IMGS;        // s0 < 28

#pragma unroll
        for (int k = 0; k < ITERS; k++) {
            if (s < SPATIAL) {                          // k=12: warp 0 only
                float4 v = *(const float4*)(tile + s * DTILE + c4);

                auto msk = [&](float fr, float fc) -> float {
                    float di = fi - fr;
                    float dj = fj - fc;
                    float l1 = fabsf(di) + fabsf(dj);   // free src-abs mods
                    return fmaxf(fmaf(l1, -TC, TAUF), -TAUF);
                };

                float4 o;
                o.x = msk(fr0, fc0) * v.x;
                o.y = msk(fr1, fc1) * v.y;
                o.z = msk(fr2, fc2) * v.z;
                o.w = msk(fr3, fc3) * v.w;
                *(float4*)(dstg + (size_t)s * DEPTH + c4) = o;
            }
            s += 16;
            // advance (i,j) by 16 positions: 16 = 14 + 2 -> one guaranteed
            // wrap, one conditional.
            fj += 2.0f;
            fi += 1.0f;
            if (fj >= (float)IMGS) { fj -= (float)IMGS; fi += 1.0f; }
        }
    }
}

extern "C" void kernel_launch(void* const* d_in, const int* in_sizes, int n_in,
                              void* d_out, int out_size) {
    (void)n_in; (void)out_size;
    const float* x = (const float*)d_in[0];
    float* out = (float*)d_out;

    int n = in_sizes[0];                                  // B * 196 * 512
    int batches = n / (SPATIAL * DEPTH);                  // 1024
    int grid = batches * (DEPTH / DTILE);                 // 16384

    // Host-side attribute call: immediate, deterministic, capture-safe.
    cudaFuncSetAttribute(mask_layer_kernel,
                         cudaFuncAttributeMaxDynamicSharedMemorySize, SMEM_BYTES);

    mask_layer_kernel<<<grid, BLOCK, SMEM_BYTES>>>(x, out);
}